// round 11
// baseline (speedup 1.0000x reference)
#include <cuda_runtime.h>
#include <math.h>

#define MAXN 50048
#define MAXE 800000
#define KIN 128
#define HID 64
#define NH 8
#define C2 40
#define NEG 0.2f
#define SXCH 36   // chunk row stride in floats (16B-aligned, conflict-free)
#define AUXB 128  // aux (count/scatter) blocks appended to each gemm1 launch

// ---------------- scratch (fp32; h1/hact pair-interleaved: float 2p=(h[p]), 2p+1=(h[p+32])) ----------------
__device__ float g_h1[MAXN * HID];
__device__ float g_alS1[MAXN * NH];
__device__ float g_alD1[MAXN * NH];
__device__ float g_hact[MAXN * HID];    // pair-interleaved
__device__ float g_h2[MAXN * C2];       // natural layout
__device__ float g_alS2[MAXN];
__device__ float g_alD2[MAXN];
// CSR
__device__ int g_cnt[MAXN];             // zero at entry (zero-init; scanC re-zeroes)
__device__ int g_incl[MAXN];
__device__ int g_rowstart[MAXN + 1];
__device__ int g_wcur[MAXN];
__device__ int g_eidx[MAXE];
__device__ int g_bsum[64];

__device__ __forceinline__ unsigned smem_u32(const void* p) {
    unsigned a;
    asm("{ .reg .u64 t; cvta.to.shared.u64 t, %1; cvt.u32.u64 %0, t; }" : "=r"(a) : "l"(p));
    return a;
}

// ---------------- scans ----------------
__global__ void scanA_k(int n) {
    __shared__ int s[1024];
    int i = blockIdx.x * 1024 + threadIdx.x;
    s[threadIdx.x] = (i < n) ? g_cnt[i] : 0;
    __syncthreads();
#pragma unroll
    for (int o = 1; o < 1024; o <<= 1) {
        int t = 0;
        if (threadIdx.x >= o) t = s[threadIdx.x - o];
        __syncthreads();
        if (threadIdx.x >= o) s[threadIdx.x] += t;
        __syncthreads();
    }
    if (i < n) g_incl[i] = s[threadIdx.x];
    if (threadIdx.x == 1023) g_bsum[blockIdx.x] = s[1023];
}

__global__ void scanC_k(int n, int E, int nb) {
    __shared__ int sb[64];
    int t = threadIdx.x;
    if (t < 64) sb[t] = (t < nb) ? g_bsum[t] : 0;
    __syncthreads();
    int i = blockIdx.x * blockDim.x + t;
    if (i == 0) g_rowstart[n] = E;
    if (i < n) {
        int b = i >> 10;
        int base = 0;
        for (int k = 0; k < b; k++) base += sb[k];
        int start = g_incl[i] - g_cnt[i] + base;
        g_rowstart[i] = start;
        g_wcur[i] = start;
        g_cnt[i] = 0;
    }
}

// ---------------- fused layer-1 GEMM (half) + aux CSR blocks ----------------
// gemm thread t: rows (t>>4)*4..+3, cols {2cg, 2cg+1, 2cg+32, 2cg+33}, cg=t&15.
// Output pair-interleaved: float4 at gr*64+4cg = (h[2cg], h[2cg+32], h[2cg+1], h[2cg+33]).
__global__ __launch_bounds__(256) void g1aux_k(
        const float* __restrict__ x, const float* __restrict__ topo,
        const float* __restrict__ W1,
        const float* __restrict__ a_src, const float* __restrict__ a_dst,
        const int* __restrict__ ei,
        int n, int E, int gblocks, int rowbase, int phase) {
    if ((int)blockIdx.x >= gblocks) {
        int tid = ((int)blockIdx.x - gblocks) * 256 + threadIdx.x;
        int stride = AUXB * 256;
        if (phase == 0) {
            for (int i = tid; i < E; i += stride)
                atomicAdd(&g_cnt[ei[E + i]], 1);
        } else {
#pragma unroll 4
            for (int i = tid; i < E; i += stride) {
                int dst = ei[E + i];
                int pos = atomicAdd(&g_wcur[dst], 1);
                g_eidx[pos] = ei[i];
            }
        }
        return;
    }

    extern __shared__ float smem[];
    float* sW  = smem;                        // 8192 floats, natural sW[k*64+c]
    float* sX0 = smem + 8192;                 // 64*36
    float* sX1 = sX0 + 64 * SXCH;             // 64*36
    float* sLS = sX1 + 64 * SXCH;             // 512
    float* sLD = sLS + 512;                   // 512
    int t = threadIdx.x;
    int row0 = (rowbase + (int)blockIdx.x) * 64;

    {
        const float4* W14 = reinterpret_cast<const float4*>(W1);
        float4* sW4w = reinterpret_cast<float4*>(sW);
        for (int i = t; i < KIN * HID / 4; i += 256) sW4w[i] = W14[i];
    }
    for (int i = t; i < 512; i += 256) { sLS[i] = 0.f; sLD[i] = 0.f; }

    int rA = t >> 3, qA = t & 7;
    int rB = (t + 256) >> 3, qB = (t + 256) & 7;
    int gsA = (row0 + rA < n) ? row0 + rA : 0;
    int gsB = (row0 + rB < n) ? row0 + rB : 0;
    const float4* xA = reinterpret_cast<const float4*>(x + gsA * 120);
    const float4* tA = reinterpret_cast<const float4*>(topo + gsA * 8);
    const float4* xB = reinterpret_cast<const float4*>(x + gsB * 120);
    const float4* tB = reinterpret_cast<const float4*>(topo + gsB * 8);
    unsigned dA0 = smem_u32(sX0 + rA * SXCH + qA * 4);
    unsigned dB0 = smem_u32(sX0 + rB * SXCH + qB * 4);
    unsigned dA1 = smem_u32(sX1 + rA * SXCH + qA * 4);
    unsigned dB1 = smem_u32(sX1 + rB * SXCH + qB * 4);

#define ISSUE_CHUNK(kc, dA, dB)                                              \
    {                                                                        \
        const float4* sA = ((kc) < 3) ? (xA + (kc) * 8 + qA)                 \
                          : ((qA < 6) ? (xA + 24 + qA) : (tA + (qA - 6)));   \
        const float4* sB = ((kc) < 3) ? (xB + (kc) * 8 + qB)                 \
                          : ((qB < 6) ? (xB + 24 + qB) : (tB + (qB - 6)));   \
        asm volatile("cp.async.cg.shared.global [%0], [%1], 16;\n"           \
                     :: "r"(dA), "l"(sA) : "memory");                        \
        asm volatile("cp.async.cg.shared.global [%0], [%1], 16;\n"           \
                     :: "r"(dB), "l"(sB) : "memory");                        \
        asm volatile("cp.async.commit_group;\n" ::: "memory");               \
    }

    ISSUE_CHUNK(0, dA0, dB0)

    int rg = t >> 4;
    int cg = t & 15;
    float acc[4][4];   // [r][0..3] = cols 2cg, 2cg+1, 2cg+32, 2cg+33
#pragma unroll
    for (int r = 0; r < 4; r++)
#pragma unroll
        for (int c = 0; c < 4; c++) acc[r][c] = 0.f;

    const float2* sW2 = reinterpret_cast<const float2*>(sW);
#pragma unroll
    for (int kc = 0; kc < 4; kc++) {
        if (kc == 0)      ISSUE_CHUNK(1, dA1, dB1)
        else if (kc == 1) ISSUE_CHUNK(2, dA0, dB0)
        else if (kc == 2) ISSUE_CHUNK(3, dA1, dB1)
        if (kc < 3) asm volatile("cp.async.wait_group 1;\n" ::: "memory");
        else        asm volatile("cp.async.wait_group 0;\n" ::: "memory");
        __syncthreads();
        const float* bx = (kc & 1) ? sX1 : sX0;
#pragma unroll 8
        for (int k = 0; k < 32; k++) {
            float2 wA = sW2[(kc * 32 + k) * 32 + cg];        // cols 2cg, 2cg+1
            float2 wB = sW2[(kc * 32 + k) * 32 + 16 + cg];   // cols 2cg+32, 2cg+33
            float xv0 = bx[(rg * 4 + 0) * SXCH + k];
            float xv1 = bx[(rg * 4 + 1) * SXCH + k];
            float xv2 = bx[(rg * 4 + 2) * SXCH + k];
            float xv3 = bx[(rg * 4 + 3) * SXCH + k];
#define STEP(r, xv) \
            acc[r][0] += xv * wA.x; acc[r][1] += xv * wA.y; \
            acc[r][2] += xv * wB.x; acc[r][3] += xv * wB.y;
            STEP(0, xv0) STEP(1, xv1) STEP(2, xv2) STEP(3, xv3)
#undef STEP
        }
        __syncthreads();
    }
#undef ISSUE_CHUNK

    // epilogue: pair-interleaved h1 + per-head logits (2 heads per thread)
    int hA = cg >> 2;          // head of cols 2cg, 2cg+1
    int hB = hA + 4;           // head of cols 2cg+32, 2cg+33
    int oA = (2 * cg) & 7;     // offset of col 2cg within head hA
    float asA0 = a_src[hA * 8 + oA],     asA1 = a_src[hA * 8 + oA + 1];
    float adA0 = a_dst[hA * 8 + oA],     adA1 = a_dst[hA * 8 + oA + 1];
    float asB0 = a_src[hB * 8 + oA],     asB1 = a_src[hB * 8 + oA + 1];
    float adB0 = a_dst[hB * 8 + oA],     adB1 = a_dst[hB * 8 + oA + 1];
    float4* g_h1_4 = reinterpret_cast<float4*>(g_h1);
#pragma unroll
    for (int r = 0; r < 4; r++) {
        int lr = rg * 4 + r;
        int gr = row0 + lr;
        if (gr < n) {
            float4 o;
            o.x = acc[r][0]; o.y = acc[r][2];   // pair 2cg:   (h[2cg],   h[2cg+32])
            o.z = acc[r][1]; o.w = acc[r][3];   // pair 2cg+1: (h[2cg+1], h[2cg+33])
            g_h1_4[gr * 16 + cg] = o;
        }
        float psA = acc[r][0] * asA0 + acc[r][1] * asA1;
        float pdA = acc[r][0] * adA0 + acc[r][1] * adA1;
        float psB = acc[r][2] * asB0 + acc[r][3] * asB1;
        float pdB = acc[r][2] * adB0 + acc[r][3] * adB1;
        atomicAdd(&sLS[lr * 8 + hA], psA);
        atomicAdd(&sLD[lr * 8 + hA], pdA);
        atomicAdd(&sLS[lr * 8 + hB], psB);
        atomicAdd(&sLD[lr * 8 + hB], pdB);
    }
    __syncthreads();
    for (int i = t; i < 512; i += 256) {
        int lr = i >> 3, h = i & 7;
        int gr = row0 + lr;
        if (gr < n) {
            g_alS1[gr * 8 + h] = sLS[i];
            g_alD1[gr * 8 + h] = sLD[i];
        }
    }
}

// ---------------- layer 1 aggregation: warp/node, 4 edges/iter, LDG.64 gathers ----------------
__global__ __launch_bounds__(256) void agg1_k(const float* __restrict__ b1, int n) {
    int w = (blockIdx.x * blockDim.x + threadIdx.x) >> 5;
    if (w >= n) return;
    int l = threadIdx.x & 31;
    int h0 = l >> 3;     // head of feature l (feature l+32 -> h0+4)
    int hh = l & 7;
    float alDh = g_alD1[w * 8 + hh];
    int beg = g_rowstart[w], end = g_rowstart[w + 1];
    float acc0 = 0.f, acc1 = 0.f, qsum = 0.f;
    // self loop
    {
        float a = g_alS1[w * 8 + hh] + alDh;
        a = a > 0.f ? a : NEG * a;
        float q = __expf(a);
        if (l < 8) qsum += q;
        float p0 = __shfl_sync(0xFFFFFFFFu, q, h0);
        float p1 = __shfl_sync(0xFFFFFFFFu, q, h0 + 4);
        float2 f = *reinterpret_cast<const float2*>(&g_h1[w * HID + 2 * l]);
        acc0 += p0 * f.x;
        acc1 += p1 * f.y;
    }
    for (int j = beg; j < end; j += 4) {
        int jj = j + h0;
        bool valid = jj < end;
        int srcv = g_eidx[valid ? jj : j];
        float a = g_alS1[srcv * 8 + hh] + alDh;
        a = a > 0.f ? a : NEG * a;
        float q = valid ? __expf(a) : 0.f;
        qsum += q;
        int nleft = end - j;
#pragma unroll
        for (int e2 = 0; e2 < 4; e2++) {
            if (e2 >= nleft) break;
            float p0 = __shfl_sync(0xFFFFFFFFu, q, e2 * 8 + h0);
            float p1 = __shfl_sync(0xFFFFFFFFu, q, e2 * 8 + h0 + 4);
            int sv = __shfl_sync(0xFFFFFFFFu, srcv, e2 * 8);
            float2 f = *reinterpret_cast<const float2*>(&g_h1[sv * HID + 2 * l]);
            acc0 += p0 * f.x;
            acc1 += p1 * f.y;
        }
    }
    qsum += __shfl_xor_sync(0xFFFFFFFFu, qsum, 8);
    qsum += __shfl_xor_sync(0xFFFFFFFFu, qsum, 16);
    float s0 = __shfl_sync(0xFFFFFFFFu, qsum, h0);
    float s1 = __shfl_sync(0xFFFFFFFFu, qsum, h0 + 4);
    float v0 = acc0 / s0 + b1[l];
    float v1 = acc1 / s1 + b1[32 + l];
    float2 o;
    o.x = v0 > 0.f ? v0 : expm1f(v0);
    o.y = v1 > 0.f ? v1 : expm1f(v1);
    *reinterpret_cast<float2*>(&g_hact[w * HID + 2 * l]) = o;   // pair-interleaved
}

// ---------------- layer 2 GEMM: reads pair-interleaved hact via W2 row permutation ----------------
__global__ __launch_bounds__(160) void gemm2_k(
        const float* __restrict__ W2,
        const float* __restrict__ a_src2, const float* __restrict__ a_dst2, int n) {
    __shared__ float sW[HID * C2];
    __shared__ float sX[64 * HID];
    __shared__ float sLS[64];
    __shared__ float sLD[64];
    int t = threadIdx.x;
    int row0 = blockIdx.x * 64;
    // permuted W2: sW row k corresponds to hact pair-layout position k
    for (int i = t; i < HID * C2; i += 160) {
        int k = i / C2, c = i - k * C2;
        int ko = (k & 1) ? (k >> 1) + 32 : (k >> 1);
        sW[i] = W2[ko * C2 + c];
    }
    for (int i = t; i < 64 * HID; i += 160) {
        int r = i >> 6, c = i & 63;
        int gr = row0 + r;
        sX[i] = (gr < n) ? g_hact[gr * HID + c] : 0.f;   // raw pair layout
    }
    if (t < 64) { sLS[t] = 0.f; sLD[t] = 0.f; }
    __syncthreads();

    int cg = t % 10;
    int rg = t / 10;
    float acc[4][4];
#pragma unroll
    for (int r = 0; r < 4; r++)
#pragma unroll
        for (int c = 0; c < 4; c++) acc[r][c] = 0.f;

    const float4* sW4 = reinterpret_cast<const float4*>(sW);
#pragma unroll 4
    for (int k = 0; k < HID; k++) {
        float4 wv = sW4[k * 10 + cg];
        float xv0 = sX[(rg * 4 + 0) * HID + k];
        float xv1 = sX[(rg * 4 + 1) * HID + k];
        float xv2 = sX[(rg * 4 + 2) * HID + k];
        float xv3 = sX[(rg * 4 + 3) * HID + k];
#define STEP(r, xv) \
        acc[r][0] += xv * wv.x; acc[r][1] += xv * wv.y; \
        acc[r][2] += xv * wv.z; acc[r][3] += xv * wv.w;
        STEP(0, xv0) STEP(1, xv1) STEP(2, xv2) STEP(3, xv3)
#undef STEP
    }

#pragma unroll
    for (int r = 0; r < 4; r++) {
        int lr = rg * 4 + r;
        int gr = row0 + lr;
        float ps = 0.f, pd = 0.f;
#pragma unroll
        for (int j = 0; j < 4; j++) {
            int c = cg * 4 + j;
            if (gr < n) g_h2[gr * C2 + c] = acc[r][j];
            ps += acc[r][j] * a_src2[c];
            pd += acc[r][j] * a_dst2[c];
        }
        atomicAdd(&sLS[lr], ps);
        atomicAdd(&sLD[lr], pd);
    }
    __syncthreads();
    if (t < 64) {
        int gr = row0 + t;
        if (gr < n) { g_alS2[gr] = sLS[t]; g_alD2[gr] = sLD[t]; }
    }
}

// ---------------- layer 2 aggregation + log_softmax: LDG.64 gathers (lanes<20 = cols 2l,2l+1) ----------------
__global__ __launch_bounds__(256) void agg2_k(const float* __restrict__ b2,
                                              float* __restrict__ out, int n) {
    int w = (blockIdx.x * blockDim.x + threadIdx.x) >> 5;
    if (w >= n) return;
    int l = threadIdx.x & 31;
    bool act = l < 20;
    float alDv = g_alD2[w];
    int beg = g_rowstart[w], end = g_rowstart[w + 1];
    float accx = 0.f, accy = 0.f, ssum = 0.f;
    // self loop
    {
        float e = g_alS2[w] + alDv;
        e = e > 0.f ? e : NEG * e;
        float p = __expf(e);
        if (l == 0) ssum += p;
        if (act) {
            float2 f = *reinterpret_cast<const float2*>(&g_h2[w * C2 + 2 * l]);
            accx += p * f.x; accy += p * f.y;
        }
    }
    for (int j = beg; j < end; j += 32) {
        int jj = j + l;
        bool valid = jj < end;
        int srcv = g_eidx[valid ? jj : j];
        float e = g_alS2[srcv] + alDv;
        e = e > 0.f ? e : NEG * e;
        float q = valid ? __expf(e) : 0.f;
        ssum += q;
        int m = min(32, end - j);
        for (int e2 = 0; e2 < m; e2++) {
            float pp = __shfl_sync(0xFFFFFFFFu, q, e2);
            int sv = __shfl_sync(0xFFFFFFFFu, srcv, e2);
            if (act) {
                float2 f = *reinterpret_cast<const float2*>(&g_h2[sv * C2 + 2 * l]);
                accx += pp * f.x; accy += pp * f.y;
            }
        }
    }
#pragma unroll
    for (int o = 16; o; o >>= 1) ssum += __shfl_xor_sync(0xFFFFFFFFu, ssum, o);
    float inv = 1.f / ssum;
    float v0 = act ? (accx * inv + b2[2 * l])     : -3.0e38f;
    float v1 = act ? (accy * inv + b2[2 * l + 1]) : -3.0e38f;
    float m = fmaxf(v0, v1);
#pragma unroll
    for (int o = 16; o; o >>= 1) m = fmaxf(m, __shfl_xor_sync(0xFFFFFFFFu, m, o));
    float se = act ? (__expf(v0 - m) + __expf(v1 - m)) : 0.f;
#pragma unroll
    for (int o = 16; o; o >>= 1) se += __shfl_xor_sync(0xFFFFFFFFu, se, o);
    float lse = logf(se) + m;
    if (act) {
        float2 o2; o2.x = v0 - lse; o2.y = v1 - lse;
        *reinterpret_cast<float2*>(&out[w * C2 + 2 * l]) = o2;
    }
}

// ---------------- launcher ----------------
extern "C" void kernel_launch(void* const* d_in, const int* in_sizes, int n_in,
                              void* d_out, int out_size) {
    const float* x    = (const float*)d_in[0];
    const float* topo = (const float*)d_in[1];
    const int*   ei   = (const int*)d_in[2];
    const float* W1   = (const float*)d_in[3];
    const float* a_s1 = (const float*)d_in[4];
    const float* a_d1 = (const float*)d_in[5];
    const float* b1   = (const float*)d_in[6];
    const float* W2   = (const float*)d_in[7];
    const float* a_s2 = (const float*)d_in[8];
    const float* a_d2 = (const float*)d_in[9];
    const float* b2   = (const float*)d_in[10];
    float* out = (float*)d_out;

    int n = in_sizes[0] / 120;
    int E = in_sizes[2] / 2;
    int nb = (n + 1023) >> 10;
    int G  = (n + 63) / 64;
    int GA = (G + 1) / 2;
    int GB = G - GA;

    const int GEMM1_SMEM = (8192 + 2 * 64 * SXCH + 1024) * 4;   // 55296 B
    cudaFuncSetAttribute(g1aux_k, cudaFuncAttributeMaxDynamicSharedMemorySize, GEMM1_SMEM);

    g1aux_k<<<GA + AUXB, 256, GEMM1_SMEM>>>(x, topo, W1, a_s1, a_d1, ei, n, E, GA, 0, 0);
    scanA_k<<<nb, 1024>>>(n);
    scanC_k<<<(n + 255) / 256, 256>>>(n, E, nb);
    g1aux_k<<<GB + AUXB, 256, GEMM1_SMEM>>>(x, topo, W1, a_s1, a_d1, ei, n, E, GB, GA, 1);
    agg1_k<<<(n * 32 + 255) / 256, 256>>>(b1, n);
    gemm2_k<<<(n + 63) / 64, 160>>>(W2, a_s2, a_d2, n);
    agg2_k<<<(n * 32 + 255) / 256, 256>>>(b2, out, n);
}

// round 13
// speedup vs baseline: 1.3975x; 1.3975x over previous
#include <cuda_runtime.h>
#include <math.h>

#define MAXN 50048
#define MAXE 800000
#define KIN 128
#define HID 64
#define NH 8
#define C2 40
#define NEG 0.2f
#define SXCH 36   // chunk row stride in floats (16B-aligned, conflict-free)

// ---------------- scratch (fp32 everywhere) ----------------
__device__ float g_h1[MAXN * HID];
__device__ float g_alS1[MAXN * NH];
__device__ float g_alD1[MAXN * NH];
__device__ float g_hact[MAXN * HID];
__device__ float g_h2[MAXN * C2];
__device__ float g_alS2[MAXN];
__device__ float g_alD2[MAXN];
// CSR
__device__ int g_cnt[MAXN];             // zero at entry (zero-init; scanC re-zeroes)
__device__ int g_incl[MAXN];
__device__ int g_rowstart[MAXN + 1];
__device__ int g_wcur[MAXN];
__device__ int g_eidx[MAXE];
__device__ int g_bsum[64];

__device__ __forceinline__ unsigned smem_u32(const void* p) {
    unsigned a;
    asm("{ .reg .u64 t; cvta.to.shared.u64 t, %1; cvt.u32.u64 %0, t; }" : "=r"(a) : "l"(p));
    return a;
}

// ---------------- CSR build ----------------
__global__ void count_k(const int* __restrict__ ei, int E) {
    int i = blockIdx.x * blockDim.x + threadIdx.x;
    if (i < E) atomicAdd(&g_cnt[ei[E + i]], 1);
}

__global__ void scanA_k(int n) {
    __shared__ int s[1024];
    int i = blockIdx.x * 1024 + threadIdx.x;
    s[threadIdx.x] = (i < n) ? g_cnt[i] : 0;
    __syncthreads();
#pragma unroll
    for (int o = 1; o < 1024; o <<= 1) {
        int t = 0;
        if (threadIdx.x >= o) t = s[threadIdx.x - o];
        __syncthreads();
        if (threadIdx.x >= o) s[threadIdx.x] += t;
        __syncthreads();
    }
    if (i < n) g_incl[i] = s[threadIdx.x];
    if (threadIdx.x == 1023) g_bsum[blockIdx.x] = s[1023];
}

__global__ void scanC_k(int n, int E, int nb) {
    __shared__ int sb[64];
    int t = threadIdx.x;
    if (t < 64) sb[t] = (t < nb) ? g_bsum[t] : 0;
    __syncthreads();
    int i = blockIdx.x * blockDim.x + t;
    if (i == 0) g_rowstart[n] = E;
    if (i < n) {
        int b = i >> 10;
        int base = 0;
        for (int k = 0; k < b; k++) base += sb[k];
        int start = g_incl[i] - g_cnt[i] + base;
        g_rowstart[i] = start;
        g_wcur[i] = start;
        g_cnt[i] = 0;
    }
}

__global__ void scatter_k(const int* __restrict__ ei, int E) {
    int i = blockIdx.x * blockDim.x + threadIdx.x;
    if (i < E) {
        int dst = ei[E + i];
        int pos = atomicAdd(&g_wcur[dst], 1);
        g_eidx[pos] = ei[i];
    }
}

// ---------------- layer 1 GEMM: cp.async double-buffered (R8) ----------------
__global__ __launch_bounds__(256) void gemm1_k(
        const float* __restrict__ x, const float* __restrict__ topo,
        const float* __restrict__ W1,
        const float* __restrict__ a_src, const float* __restrict__ a_dst, int n) {
    extern __shared__ float smem[];
    float* sW  = smem;                        // 8192 floats
    float* sX0 = smem + 8192;                 // 64*36
    float* sX1 = sX0 + 64 * SXCH;             // 64*36
    float* sLS = sX1 + 64 * SXCH;             // 512
    float* sLD = sLS + 512;                   // 512
    int t = threadIdx.x;
    int row0 = blockIdx.x * 64;

    {
        const float4* W14 = reinterpret_cast<const float4*>(W1);
        float4* sW4w = reinterpret_cast<float4*>(sW);
        for (int i = t; i < KIN * HID / 4; i += 256) sW4w[i] = W14[i];
    }
    for (int i = t; i < 512; i += 256) { sLS[i] = 0.f; sLD[i] = 0.f; }

    int rA = t >> 3, qA = t & 7;
    int rB = (t + 256) >> 3, qB = (t + 256) & 7;
    int gsA = (row0 + rA < n) ? row0 + rA : 0;
    int gsB = (row0 + rB < n) ? row0 + rB : 0;
    const float4* xA = reinterpret_cast<const float4*>(x + gsA * 120);
    const float4* tA = reinterpret_cast<const float4*>(topo + gsA * 8);
    const float4* xB = reinterpret_cast<const float4*>(x + gsB * 120);
    const float4* tB = reinterpret_cast<const float4*>(topo + gsB * 8);
    unsigned dA0 = smem_u32(sX0 + rA * SXCH + qA * 4);
    unsigned dB0 = smem_u32(sX0 + rB * SXCH + qB * 4);
    unsigned dA1 = smem_u32(sX1 + rA * SXCH + qA * 4);
    unsigned dB1 = smem_u32(sX1 + rB * SXCH + qB * 4);

#define ISSUE_CHUNK(kc, dA, dB)                                              \
    {                                                                        \
        const float4* sA = ((kc) < 3) ? (xA + (kc) * 8 + qA)                 \
                          : ((qA < 6) ? (xA + 24 + qA) : (tA + (qA - 6)));   \
        const float4* sB = ((kc) < 3) ? (xB + (kc) * 8 + qB)                 \
                          : ((qB < 6) ? (xB + 24 + qB) : (tB + (qB - 6)));   \
        asm volatile("cp.async.cg.shared.global [%0], [%1], 16;\n"           \
                     :: "r"(dA), "l"(sA) : "memory");                        \
        asm volatile("cp.async.cg.shared.global [%0], [%1], 16;\n"           \
                     :: "r"(dB), "l"(sB) : "memory");                        \
        asm volatile("cp.async.commit_group;\n" ::: "memory");               \
    }

    ISSUE_CHUNK(0, dA0, dB0)

    int rg = t >> 4;
    int cg = t & 15;
    float acc[4][4];
#pragma unroll
    for (int r = 0; r < 4; r++)
#pragma unroll
        for (int c = 0; c < 4; c++) acc[r][c] = 0.f;

    const float4* sW4 = reinterpret_cast<const float4*>(sW);
#pragma unroll
    for (int kc = 0; kc < 4; kc++) {
        if (kc == 0)      ISSUE_CHUNK(1, dA1, dB1)
        else if (kc == 1) ISSUE_CHUNK(2, dA0, dB0)
        else if (kc == 2) ISSUE_CHUNK(3, dA1, dB1)
        if (kc < 3) asm volatile("cp.async.wait_group 1;\n" ::: "memory");
        else        asm volatile("cp.async.wait_group 0;\n" ::: "memory");
        __syncthreads();
        const float* bx = (kc & 1) ? sX1 : sX0;
#pragma unroll 8
        for (int k = 0; k < 32; k++) {
            float4 wv = sW4[(kc * 32 + k) * 16 + cg];
            float xv0 = bx[(rg * 4 + 0) * SXCH + k];
            float xv1 = bx[(rg * 4 + 1) * SXCH + k];
            float xv2 = bx[(rg * 4 + 2) * SXCH + k];
            float xv3 = bx[(rg * 4 + 3) * SXCH + k];
#define STEP(r, xv) \
            acc[r][0] += xv * wv.x; acc[r][1] += xv * wv.y; \
            acc[r][2] += xv * wv.z; acc[r][3] += xv * wv.w;
            STEP(0, xv0) STEP(1, xv1) STEP(2, xv2) STEP(3, xv3)
#undef STEP
        }
        __syncthreads();
    }
#undef ISSUE_CHUNK

    int hd = cg >> 1;
    int off = (cg & 1) * 4;
    float4* g_h1_4 = reinterpret_cast<float4*>(g_h1);
#pragma unroll
    for (int r = 0; r < 4; r++) {
        int lr = rg * 4 + r;
        int gr = row0 + lr;
        if (gr < n) {
            float4 o;
            o.x = acc[r][0]; o.y = acc[r][1]; o.z = acc[r][2]; o.w = acc[r][3];
            g_h1_4[gr * 16 + cg] = o;
        }
        float ps = 0.f, pd = 0.f;
#pragma unroll
        for (int j = 0; j < 4; j++) {
            ps += acc[r][j] * a_src[hd * 8 + off + j];
            pd += acc[r][j] * a_dst[hd * 8 + off + j];
        }
        atomicAdd(&sLS[lr * 8 + hd], ps);
        atomicAdd(&sLD[lr * 8 + hd], pd);
    }
    __syncthreads();
    for (int i = t; i < 512; i += 256) {
        int lr = i >> 3, h = i & 7;
        int gr = row0 + lr;
        if (gr < n) {
            g_alS1[gr * 8 + h] = sLS[i];
            g_alD1[gr * 8 + h] = sLD[i];
        }
    }
}

// ---------------- layer 1 aggregation: TWO warps per node (feature halves), 8 edges/iter ----------------
// warp w2: node w = w2>>1, half hf = w2&1 -> features hf*32 + l.
// Logit phase lane layout: edge slot e8 = l>>2 (8 edges), head hh = hf*4 + (l&3).
__global__ __launch_bounds__(256) void agg1_k(const float* __restrict__ b1, int n) {
    int w2 = (blockIdx.x * blockDim.x + threadIdx.x) >> 5;
    int w = w2 >> 1;
    if (w >= n) return;
    int hf = w2 & 1;
    int l = threadIdx.x & 31;
    int f = hf * 32 + l;                 // feature this lane accumulates
    int fh = l >> 3;                     // head-in-half of feature f (0..3)
    int hh = hf * 4 + (l & 3);           // head this lane evaluates in logit phase
    float alDh = g_alD1[w * 8 + hh];
    int beg = g_rowstart[w], end = g_rowstart[w + 1];
    float acc = 0.f, qsum = 0.f;
    // self loop
    {
        float a = g_alS1[w * 8 + hh] + alDh;
        a = a > 0.f ? a : NEG * a;
        float q = __expf(a);
        if (l < 4) qsum += q;            // count once per head (slot 0 lanes)
        float p = __shfl_sync(0xFFFFFFFFu, q, fh);   // lane fh holds head hf*4+fh (e8=0)
        acc += p * g_h1[w * HID + f];
    }
    for (int j = beg; j < end; j += 8) {
        int e8 = l >> 2;
        int jj = j + e8;
        bool valid = jj < end;
        int srcv = g_eidx[valid ? jj : j];
        float a = g_alS1[srcv * 8 + hh] + alDh;
        a = a > 0.f ? a : NEG * a;
        float q = valid ? __expf(a) : 0.f;
        qsum += q;
        int nleft = end - j;             // warp-uniform
#pragma unroll
        for (int e2 = 0; e2 < 8; e2++) {
            if (e2 >= nleft) break;      // warp-uniform
            float p = __shfl_sync(0xFFFFFFFFu, q, e2 * 4 + fh);
            int sv = __shfl_sync(0xFFFFFFFFu, srcv, e2 * 4);
            acc += p * g_h1[sv * HID + f];
        }
    }
    // reduce qsum over the 8 edge slots (lanes sharing l&3)
    qsum += __shfl_xor_sync(0xFFFFFFFFu, qsum, 4);
    qsum += __shfl_xor_sync(0xFFFFFFFFu, qsum, 8);
    qsum += __shfl_xor_sync(0xFFFFFFFFu, qsum, 16);
    float s = __shfl_sync(0xFFFFFFFFu, qsum, fh);    // lane fh: l&3 == fh -> head hf*4+fh total
    float v = acc / s + b1[f];
    g_hact[w * HID + f] = v > 0.f ? v : expm1f(v);
}

// ---------------- layer 2 GEMM (R8) ----------------
__global__ __launch_bounds__(160) void gemm2_k(
        const float* __restrict__ W2,
        const float* __restrict__ a_src2, const float* __restrict__ a_dst2, int n) {
    __shared__ float sW[HID * C2];
    __shared__ float sX[64 * HID];
    __shared__ float sLS[64];
    __shared__ float sLD[64];
    int t = threadIdx.x;
    int row0 = blockIdx.x * 64;
    for (int i = t; i < HID * C2; i += 160) sW[i] = W2[i];
    for (int i = t; i < 64 * HID; i += 160) {
        int r = i >> 6, c = i & 63;
        int gr = row0 + r;
        sX[i] = (gr < n) ? g_hact[gr * HID + c] : 0.f;
    }
    if (t < 64) { sLS[t] = 0.f; sLD[t] = 0.f; }
    __syncthreads();

    int cg = t % 10;
    int rg = t / 10;
    float acc[4][4];
#pragma unroll
    for (int r = 0; r < 4; r++)
#pragma unroll
        for (int c = 0; c < 4; c++) acc[r][c] = 0.f;

    const float4* sW4 = reinterpret_cast<const float4*>(sW);
#pragma unroll 4
    for (int k = 0; k < HID; k++) {
        float4 wv = sW4[k * 10 + cg];
        float xv0 = sX[(rg * 4 + 0) * HID + k];
        float xv1 = sX[(rg * 4 + 1) * HID + k];
        float xv2 = sX[(rg * 4 + 2) * HID + k];
        float xv3 = sX[(rg * 4 + 3) * HID + k];
#define STEP(r, xv) \
        acc[r][0] += xv * wv.x; acc[r][1] += xv * wv.y; \
        acc[r][2] += xv * wv.z; acc[r][3] += xv * wv.w;
        STEP(0, xv0) STEP(1, xv1) STEP(2, xv2) STEP(3, xv3)
#undef STEP
    }

#pragma unroll
    for (int r = 0; r < 4; r++) {
        int lr = rg * 4 + r;
        int gr = row0 + lr;
        float ps = 0.f, pd = 0.f;
#pragma unroll
        for (int j = 0; j < 4; j++) {
            int c = cg * 4 + j;
            if (gr < n) g_h2[gr * C2 + c] = acc[r][j];
            ps += acc[r][j] * a_src2[c];
            pd += acc[r][j] * a_dst2[c];
        }
        atomicAdd(&sLS[lr], ps);
        atomicAdd(&sLD[lr], pd);
    }
    __syncthreads();
    if (t < 64) {
        int gr = row0 + t;
        if (gr < n) { g_alS2[gr] = sLS[t]; g_alD2[gr] = sLD[t]; }
    }
}

// ---------------- layer 2 aggregation + log_softmax (R8) ----------------
__global__ __launch_bounds__(256) void agg2_k(const float* __restrict__ b2,
                                              float* __restrict__ out, int n) {
    int w = (blockIdx.x * blockDim.x + threadIdx.x) >> 5;
    if (w >= n) return;
    int l = threadIdx.x & 31;
    float alDv = g_alD2[w];
    int beg = g_rowstart[w], end = g_rowstart[w + 1];
    float acc0 = 0.f, acc1 = 0.f, ssum = 0.f;
    {
        float e = g_alS2[w] + alDv;
        e = e > 0.f ? e : NEG * e;
        float p = __expf(e);
        if (l == 0) ssum += p;
        acc0 += p * g_h2[w * C2 + l];
        if (l < 8) acc1 += p * g_h2[w * C2 + 32 + l];
    }
    for (int j = beg; j < end; j += 32) {
        int jj = j + l;
        bool valid = jj < end;
        int srcv = g_eidx[valid ? jj : j];
        float e = g_alS2[srcv] + alDv;
        e = e > 0.f ? e : NEG * e;
        float q = valid ? __expf(e) : 0.f;
        ssum += q;
        int m = min(32, end - j);
        for (int e2 = 0; e2 < m; e2++) {
            float pp = __shfl_sync(0xFFFFFFFFu, q, e2);
            int sv = __shfl_sync(0xFFFFFFFFu, srcv, e2);
            acc0 += pp * g_h2[sv * C2 + l];
            if (l < 8) acc1 += pp * g_h2[sv * C2 + 32 + l];
        }
    }
#pragma unroll
    for (int o = 16; o; o >>= 1) ssum += __shfl_xor_sync(0xFFFFFFFFu, ssum, o);
    float inv = 1.f / ssum;
    float v0 = acc0 * inv + b2[l];
    float v1 = (l < 8) ? (acc1 * inv + b2[32 + l]) : -3.0e38f;
    float m = fmaxf(v0, v1);
#pragma unroll
    for (int o = 16; o; o >>= 1) m = fmaxf(m, __shfl_xor_sync(0xFFFFFFFFu, m, o));
    float se = __expf(v0 - m) + ((l < 8) ? __expf(v1 - m) : 0.f);
#pragma unroll
    for (int o = 16; o; o >>= 1) se += __shfl_xor_sync(0xFFFFFFFFu, se, o);
    float lse = logf(se) + m;
    out[w * C2 + l] = v0 - lse;
    if (l < 8) out[w * C2 + 32 + l] = v1 - lse;
}

// ---------------- launcher ----------------
extern "C" void kernel_launch(void* const* d_in, const int* in_sizes, int n_in,
                              void* d_out, int out_size) {
    const float* x    = (const float*)d_in[0];
    const float* topo = (const float*)d_in[1];
    const int*   ei   = (const int*)d_in[2];
    const float* W1   = (const float*)d_in[3];
    const float* a_s1 = (const float*)d_in[4];
    const float* a_d1 = (const float*)d_in[5];
    const float* b1   = (const float*)d_in[6];
    const float* W2   = (const float*)d_in[7];
    const float* a_s2 = (const float*)d_in[8];
    const float* a_d2 = (const float*)d_in[9];
    const float* b2   = (const float*)d_in[10];
    float* out = (float*)d_out;

    int n = in_sizes[0] / 120;
    int E = in_sizes[2] / 2;
    int nb = (n + 1023) >> 10;

    const int GEMM1_SMEM = (8192 + 2 * 64 * SXCH + 1024) * 4;   // 55296 B
    cudaFuncSetAttribute(gemm1_k, cudaFuncAttributeMaxDynamicSharedMemorySize, GEMM1_SMEM);

    count_k<<<(E + 255) / 256, 256>>>(ei, E);
    scanA_k<<<nb, 1024>>>(n);
    scanC_k<<<(n + 255) / 256, 256>>>(n, E, nb);
    gemm1_k<<<(n + 63) / 64, 256, GEMM1_SMEM>>>(x, topo, W1, a_s1, a_d1, n);
    scatter_k<<<(E + 255) / 256, 256>>>(ei, E);
    agg1_k<<<(n * 64 + 255) / 256, 256>>>(b1, n);    // 2 warps per node
    gemm2_k<<<(n + 63) / 64, 160>>>(W2, a_s2, a_d2, n);
    agg2_k<<<(n * 32 + 255) / 256, 256>>>(b2, out, n);
}

// round 14
// speedup vs baseline: 1.5338x; 1.0976x over previous
#include <cuda_runtime.h>
#include <math.h>

#define MAXN 50048
#define MAXE 800000
#define KIN 128
#define HID 64
#define NH 8
#define C2 40
#define NEG 0.2f
#define SXCH 36   // chunk row stride in floats (16B-aligned, conflict-free)

// ---------------- scratch (fp32 everywhere) ----------------
__device__ float g_h1[MAXN * HID];
__device__ float g_alS1[MAXN * NH];
__device__ float g_alD1[MAXN * NH];
__device__ float g_hact[MAXN * HID];
__device__ float g_h2[MAXN * C2];
__device__ float g_alS2[MAXN];
__device__ float g_alD2[MAXN];
// CSR
__device__ int g_cnt[MAXN];             // zero at entry (zero-init; scanC re-zeroes)
__device__ int g_incl[MAXN];
__device__ int g_rowstart[MAXN + 1];
__device__ int g_wcur[MAXN];
__device__ int g_eidx[MAXE];
__device__ int g_bsum[64];

__device__ __forceinline__ unsigned smem_u32(const void* p) {
    unsigned a;
    asm("{ .reg .u64 t; cvta.to.shared.u64 t, %1; cvt.u32.u64 %0, t; }" : "=r"(a) : "l"(p));
    return a;
}

// ---------------- scans ----------------
__global__ void scanA_k(int n) {
    __shared__ int s[1024];
    int i = blockIdx.x * 1024 + threadIdx.x;
    s[threadIdx.x] = (i < n) ? g_cnt[i] : 0;
    __syncthreads();
#pragma unroll
    for (int o = 1; o < 1024; o <<= 1) {
        int t = 0;
        if (threadIdx.x >= o) t = s[threadIdx.x - o];
        __syncthreads();
        if (threadIdx.x >= o) s[threadIdx.x] += t;
        __syncthreads();
    }
    if (i < n) g_incl[i] = s[threadIdx.x];
    if (threadIdx.x == 1023) g_bsum[blockIdx.x] = s[1023];
}

__global__ void scanC_k(int n, int E, int nb) {
    __shared__ int sb[64];
    int t = threadIdx.x;
    if (t < 64) sb[t] = (t < nb) ? g_bsum[t] : 0;
    __syncthreads();
    int i = blockIdx.x * blockDim.x + t;
    if (i == 0) g_rowstart[n] = E;
    if (i < n) {
        int b = i >> 10;
        int base = 0;
        for (int k = 0; k < b; k++) base += sb[k];
        int start = g_incl[i] - g_cnt[i] + base;
        g_rowstart[i] = start;
        g_wcur[i] = start;
        g_cnt[i] = 0;
    }
}

// ---------------- layer-1 GEMM half + in-block CSR aux ----------------
// Every block does its 64-row gemm tile AND an edge slice (batched early,
// atomics drain under the gemm main loop). phase 0 = count, 1 = scatter.
__global__ __launch_bounds__(256) void g1aux_k(
        const float* __restrict__ x, const float* __restrict__ topo,
        const float* __restrict__ W1,
        const float* __restrict__ a_src, const float* __restrict__ a_dst,
        const int* __restrict__ ei,
        int n, int E, int rowbase, int phase) {
    extern __shared__ float smem[];
    float* sW  = smem;                        // 8192 floats
    float* sX0 = smem + 8192;                 // 64*36
    float* sX1 = sX0 + 64 * SXCH;             // 64*36
    float* sLS = sX1 + 64 * SXCH;             // 512
    float* sLD = sLS + 512;                   // 512
    int t = threadIdx.x;
    int row0 = (rowbase + (int)blockIdx.x) * 64;

    // ---- cp.async setup + first chunk issue (as in R8) ----
    int rA = t >> 3, qA = t & 7;
    int rB = (t + 256) >> 3, qB = (t + 256) & 7;
    int gsA = (row0 + rA < n) ? row0 + rA : 0;
    int gsB = (row0 + rB < n) ? row0 + rB : 0;
    const float4* xA = reinterpret_cast<const float4*>(x + gsA * 120);
    const float4* tA = reinterpret_cast<const float4*>(topo + gsA * 8);
    const float4* xB = reinterpret_cast<const float4*>(x + gsB * 120);
    const float4* tB = reinterpret_cast<const float4*>(topo + gsB * 8);
    unsigned dA0 = smem_u32(sX0 + rA * SXCH + qA * 4);
    unsigned dB0 = smem_u32(sX0 + rB * SXCH + qB * 4);
    unsigned dA1 = smem_u32(sX1 + rA * SXCH + qA * 4);
    unsigned dB1 = smem_u32(sX1 + rB * SXCH + qB * 4);

#define ISSUE_CHUNK(kc, dA, dB)                                              \
    {                                                                        \
        const float4* sA = ((kc) < 3) ? (xA + (kc) * 8 + qA)                 \
                          : ((qA < 6) ? (xA + 24 + qA) : (tA + (qA - 6)));   \
        const float4* sB = ((kc) < 3) ? (xB + (kc) * 8 + qB)                 \
                          : ((qB < 6) ? (xB + 24 + qB) : (tB + (qB - 6)));   \
        asm volatile("cp.async.cg.shared.global [%0], [%1], 16;\n"           \
                     :: "r"(dA), "l"(sA) : "memory");                        \
        asm volatile("cp.async.cg.shared.global [%0], [%1], 16;\n"           \
                     :: "r"(dB), "l"(sB) : "memory");                        \
        asm volatile("cp.async.commit_group;\n" ::: "memory");               \
    }

    ISSUE_CHUNK(0, dA0, dB0)

    // ---- W load ----
    {
        const float4* W14 = reinterpret_cast<const float4*>(W1);
        float4* sW4w = reinterpret_cast<float4*>(sW);
        for (int i = t; i < KIN * HID / 4; i += 256) sW4w[i] = W14[i];
    }
    for (int i = t; i < 512; i += 256) { sLS[i] = 0.f; sLD[i] = 0.f; }

    // ---- aux edge slice: batched loads then atomics (drain under gemm) ----
    {
        int epb = (E + gridDim.x - 1) / gridDim.x;
        int e0 = (int)blockIdx.x * epb;
        int e1 = min(E, e0 + epb);
        int base = e0 + t;
        int d[8], s[8];
#pragma unroll
        for (int u = 0; u < 8; u++) {
            int i = base + u * 256;
            bool v = i < e1;
            d[u] = v ? ei[E + i] : -1;
            s[u] = v ? ei[i] : 0;
        }
        if (phase == 0) {
#pragma unroll
            for (int u = 0; u < 8; u++)
                if (d[u] >= 0) atomicAdd(&g_cnt[d[u]], 1);
        } else {
            int pos[8];
#pragma unroll
            for (int u = 0; u < 8; u++)
                pos[u] = (d[u] >= 0) ? atomicAdd(&g_wcur[d[u]], 1) : 0;
#pragma unroll
            for (int u = 0; u < 8; u++)
                if (d[u] >= 0) g_eidx[pos[u]] = s[u];
        }
        // safety tail (no-op for expected grid sizes)
        for (int i = base + 8 * 256; i < e1; i += 256) {
            int dd = ei[E + i];
            if (phase == 0) atomicAdd(&g_cnt[dd], 1);
            else { int pp = atomicAdd(&g_wcur[dd], 1); g_eidx[pp] = ei[i]; }
        }
    }
    __syncthreads();

    // ---- gemm main loop (R8) ----
    int rg = t >> 4;
    int cg = t & 15;
    float acc[4][4];
#pragma unroll
    for (int r = 0; r < 4; r++)
#pragma unroll
        for (int c = 0; c < 4; c++) acc[r][c] = 0.f;

    const float4* sW4 = reinterpret_cast<const float4*>(sW);
#pragma unroll
    for (int kc = 0; kc < 4; kc++) {
        if (kc == 0)      ISSUE_CHUNK(1, dA1, dB1)
        else if (kc == 1) ISSUE_CHUNK(2, dA0, dB0)
        else if (kc == 2) ISSUE_CHUNK(3, dA1, dB1)
        if (kc < 3) asm volatile("cp.async.wait_group 1;\n" ::: "memory");
        else        asm volatile("cp.async.wait_group 0;\n" ::: "memory");
        __syncthreads();
        const float* bx = (kc & 1) ? sX1 : sX0;
#pragma unroll 8
        for (int k = 0; k < 32; k++) {
            float4 wv = sW4[(kc * 32 + k) * 16 + cg];
            float xv0 = bx[(rg * 4 + 0) * SXCH + k];
            float xv1 = bx[(rg * 4 + 1) * SXCH + k];
            float xv2 = bx[(rg * 4 + 2) * SXCH + k];
            float xv3 = bx[(rg * 4 + 3) * SXCH + k];
#define STEP(r, xv) \
            acc[r][0] += xv * wv.x; acc[r][1] += xv * wv.y; \
            acc[r][2] += xv * wv.z; acc[r][3] += xv * wv.w;
            STEP(0, xv0) STEP(1, xv1) STEP(2, xv2) STEP(3, xv3)
#undef STEP
        }
        __syncthreads();
    }
#undef ISSUE_CHUNK

    int hd = cg >> 1;
    int off = (cg & 1) * 4;
    float4* g_h1_4 = reinterpret_cast<float4*>(g_h1);
#pragma unroll
    for (int r = 0; r < 4; r++) {
        int lr = rg * 4 + r;
        int gr = row0 + lr;
        if (gr < n) {
            float4 o;
            o.x = acc[r][0]; o.y = acc[r][1]; o.z = acc[r][2]; o.w = acc[r][3];
            g_h1_4[gr * 16 + cg] = o;
        }
        float ps = 0.f, pd = 0.f;
#pragma unroll
        for (int j = 0; j < 4; j++) {
            ps += acc[r][j] * a_src[hd * 8 + off + j];
            pd += acc[r][j] * a_dst[hd * 8 + off + j];
        }
        atomicAdd(&sLS[lr * 8 + hd], ps);
        atomicAdd(&sLD[lr * 8 + hd], pd);
    }
    __syncthreads();
    for (int i = t; i < 512; i += 256) {
        int lr = i >> 3, h = i & 7;
        int gr = row0 + lr;
        if (gr < n) {
            g_alS1[gr * 8 + h] = sLS[i];
            g_alD1[gr * 8 + h] = sLD[i];
        }
    }
}

// ---------------- layer 1 aggregation (R8/R5, warp per node) ----------------
__global__ __launch_bounds__(256) void agg1_k(const float* __restrict__ b1, int n) {
    int w = (blockIdx.x * blockDim.x + threadIdx.x) >> 5;
    if (w >= n) return;
    int l = threadIdx.x & 31;
    int h0 = l >> 3;
    int hh = l & 7;
    float alDh = g_alD1[w * 8 + hh];
    int beg = g_rowstart[w], end = g_rowstart[w + 1];
    float acc0 = 0.f, acc1 = 0.f, qsum = 0.f;
    {
        float a = g_alS1[w * 8 + hh] + alDh;
        a = a > 0.f ? a : NEG * a;
        float q = __expf(a);
        if (l < 8) qsum += q;
        float p0 = __shfl_sync(0xFFFFFFFFu, q, h0);
        float p1 = __shfl_sync(0xFFFFFFFFu, q, h0 + 4);
        acc0 += p0 * g_h1[w * HID + l];
        acc1 += p1 * g_h1[w * HID + 32 + l];
    }
    for (int j = beg; j < end; j += 4) {
        int jj = j + h0;
        bool valid = jj < end;
        int srcv = g_eidx[valid ? jj : j];
        float a = g_alS1[srcv * 8 + hh] + alDh;
        a = a > 0.f ? a : NEG * a;
        float q = valid ? __expf(a) : 0.f;
        qsum += q;
        int nleft = end - j;
#pragma unroll
        for (int e2 = 0; e2 < 4; e2++) {
            if (e2 >= nleft) break;
            float p0 = __shfl_sync(0xFFFFFFFFu, q, e2 * 8 + h0);
            float p1 = __shfl_sync(0xFFFFFFFFu, q, e2 * 8 + h0 + 4);
            int sv = __shfl_sync(0xFFFFFFFFu, srcv, e2 * 8);
            acc0 += p0 * g_h1[sv * HID + l];
            acc1 += p1 * g_h1[sv * HID + 32 + l];
        }
    }
    qsum += __shfl_xor_sync(0xFFFFFFFFu, qsum, 8);
    qsum += __shfl_xor_sync(0xFFFFFFFFu, qsum, 16);
    float s0 = __shfl_sync(0xFFFFFFFFu, qsum, h0);
    float s1 = __shfl_sync(0xFFFFFFFFu, qsum, h0 + 4);
    float v0 = acc0 / s0 + b1[l];
    float v1 = acc1 / s1 + b1[32 + l];
    g_hact[w * HID + l]      = v0 > 0.f ? v0 : expm1f(v0);
    g_hact[w * HID + 32 + l] = v1 > 0.f ? v1 : expm1f(v1);
}

// ---------------- layer 2 GEMM (R8) ----------------
__global__ __launch_bounds__(160) void gemm2_k(
        const float* __restrict__ W2,
        const float* __restrict__ a_src2, const float* __restrict__ a_dst2, int n) {
    __shared__ float sW[HID * C2];
    __shared__ float sX[64 * HID];
    __shared__ float sLS[64];
    __shared__ float sLD[64];
    int t = threadIdx.x;
    int row0 = blockIdx.x * 64;
    for (int i = t; i < HID * C2; i += 160) sW[i] = W2[i];
    for (int i = t; i < 64 * HID; i += 160) {
        int r = i >> 6, c = i & 63;
        int gr = row0 + r;
        sX[i] = (gr < n) ? g_hact[gr * HID + c] : 0.f;
    }
    if (t < 64) { sLS[t] = 0.f; sLD[t] = 0.f; }
    __syncthreads();

    int cg = t % 10;
    int rg = t / 10;
    float acc[4][4];
#pragma unroll
    for (int r = 0; r < 4; r++)
#pragma unroll
        for (int c = 0; c < 4; c++) acc[r][c] = 0.f;

    const float4* sW4 = reinterpret_cast<const float4*>(sW);
#pragma unroll 4
    for (int k = 0; k < HID; k++) {
        float4 wv = sW4[k * 10 + cg];
        float xv0 = sX[(rg * 4 + 0) * HID + k];
        float xv1 = sX[(rg * 4 + 1) * HID + k];
        float xv2 = sX[(rg * 4 + 2) * HID + k];
        float xv3 = sX[(rg * 4 + 3) * HID + k];
#define STEP(r, xv) \
        acc[r][0] += xv * wv.x; acc[r][1] += xv * wv.y; \
        acc[r][2] += xv * wv.z; acc[r][3] += xv * wv.w;
        STEP(0, xv0) STEP(1, xv1) STEP(2, xv2) STEP(3, xv3)
#undef STEP
    }

#pragma unroll
    for (int r = 0; r < 4; r++) {
        int lr = rg * 4 + r;
        int gr = row0 + lr;
        float ps = 0.f, pd = 0.f;
#pragma unroll
        for (int j = 0; j < 4; j++) {
            int c = cg * 4 + j;
            if (gr < n) g_h2[gr * C2 + c] = acc[r][j];
            ps += acc[r][j] * a_src2[c];
            pd += acc[r][j] * a_dst2[c];
        }
        atomicAdd(&sLS[lr], ps);
        atomicAdd(&sLD[lr], pd);
    }
    __syncthreads();
    if (t < 64) {
        int gr = row0 + t;
        if (gr < n) { g_alS2[gr] = sLS[t]; g_alD2[gr] = sLD[t]; }
    }
}

// ---------------- layer 2 aggregation + log_softmax (R8) ----------------
__global__ __launch_bounds__(256) void agg2_k(const float* __restrict__ b2,
                                              float* __restrict__ out, int n) {
    int w = (blockIdx.x * blockDim.x + threadIdx.x) >> 5;
    if (w >= n) return;
    int l = threadIdx.x & 31;
    float alDv = g_alD2[w];
    int beg = g_rowstart[w], end = g_rowstart[w + 1];
    float acc0 = 0.f, acc1 = 0.f, ssum = 0.f;
    {
        float e = g_alS2[w] + alDv;
        e = e > 0.f ? e : NEG * e;
        float p = __expf(e);
        if (l == 0) ssum += p;
        acc0 += p * g_h2[w * C2 + l];
        if (l < 8) acc1 += p * g_h2[w * C2 + 32 + l];
    }
    for (int j = beg; j < end; j += 32) {
        int jj = j + l;
        bool valid = jj < end;
        int srcv = g_eidx[valid ? jj : j];
        float e = g_alS2[srcv] + alDv;
        e = e > 0.f ? e : NEG * e;
        float q = valid ? __expf(e) : 0.f;
        ssum += q;
        int m = min(32, end - j);
        for (int e2 = 0; e2 < m; e2++) {
            float pp = __shfl_sync(0xFFFFFFFFu, q, e2);
            int sv = __shfl_sync(0xFFFFFFFFu, srcv, e2);
            acc0 += pp * g_h2[sv * C2 + l];
            if (l < 8) acc1 += pp * g_h2[sv * C2 + 32 + l];
        }
    }
#pragma unroll
    for (int o = 16; o; o >>= 1) ssum += __shfl_xor_sync(0xFFFFFFFFu, ssum, o);
    float inv = 1.f / ssum;
    float v0 = acc0 * inv + b2[l];
    float v1 = (l < 8) ? (acc1 * inv + b2[32 + l]) : -3.0e38f;
    float m = fmaxf(v0, v1);
#pragma unroll
    for (int o = 16; o; o >>= 1) m = fmaxf(m, __shfl_xor_sync(0xFFFFFFFFu, m, o));
    float se = __expf(v0 - m) + ((l < 8) ? __expf(v1 - m) : 0.f);
#pragma unroll
    for (int o = 16; o; o >>= 1) se += __shfl_xor_sync(0xFFFFFFFFu, se, o);
    float lse = logf(se) + m;
    out[w * C2 + l] = v0 - lse;
    if (l < 8) out[w * C2 + 32 + l] = v1 - lse;
}

// ---------------- launcher ----------------
extern "C" void kernel_launch(void* const* d_in, const int* in_sizes, int n_in,
                              void* d_out, int out_size) {
    const float* x    = (const float*)d_in[0];
    const float* topo = (const float*)d_in[1];
    const int*   ei   = (const int*)d_in[2];
    const float* W1   = (const float*)d_in[3];
    const float* a_s1 = (const float*)d_in[4];
    const float* a_d1 = (const float*)d_in[5];
    const float* b1   = (const float*)d_in[6];
    const float* W2   = (const float*)d_in[7];
    const float* a_s2 = (const float*)d_in[8];
    const float* a_d2 = (const float*)d_in[9];
    const float* b2   = (const float*)d_in[10];
    float* out = (float*)d_out;

    int n = in_sizes[0] / 120;
    int E = in_sizes[2] / 2;
    int nb = (n + 1023) >> 10;
    int G  = (n + 63) / 64;
    int GA = (G + 1) / 2;
    int GB = G - GA;

    const int GEMM1_SMEM = (8192 + 2 * 64 * SXCH + 1024) * 4;   // 55296 B
    cudaFuncSetAttribute(g1aux_k, cudaFuncAttributeMaxDynamicSharedMemorySize, GEMM1_SMEM);

    // gemm1 half A + count (count atomics drain under gemm compute)
    g1aux_k<<<GA, 256, GEMM1_SMEM>>>(x, topo, W1, a_s1, a_d1, ei, n, E, 0, 0);
    scanA_k<<<nb, 1024>>>(n);
    scanC_k<<<(n + 255) / 256, 256>>>(n, E, nb);
    // gemm1 half B + scatter (scatter needs scanC; gemm rows independent)
    g1aux_k<<<GB, 256, GEMM1_SMEM>>>(x, topo, W1, a_s1, a_d1, ei, n, E, GA, 1);
    agg1_k<<<(n * 32 + 255) / 256, 256>>>(b1, n);
    gemm2_k<<<(n + 63) / 64, 160>>>(W2, a_s2, a_d2, n);
    agg2_k<<<(n * 32 + 255) / 256, 256>>>(b2, out, n);
}